// round 10
// baseline (speedup 1.0000x reference)
#include <cuda_runtime.h>
#include <cuda_fp16.h>
#include <cstdint>

#define TT 2048
#define CC 1024
#define NH 16
#define BB 2
#define NHC (NH*CC)   // 16384

// ---- static device scratch (no allocation anywhere) ----
__device__ __align__(16) __half g_ph [(size_t)BB*NH*TT*TT];  // 256 MB fp16 unnorm P
__device__ __align__(16) __half g_oh [(size_t)BB*TT*NHC];    // 128 MB fp16 O
__device__ __align__(16) __half g_xh [(size_t)BB*TT*CC];     //   8 MB fp16 x
__device__ __align__(16) __half g_xTh[(size_t)BB*CC*TT];     //   8 MB fp16 x^T
__device__ __align__(16) __half g_wTh[(size_t)CC*NHC];       //  32 MB fp16 W^T

// ---------------------------------------------------------------------------
// helpers (family-wide PTX only: cp.async / ldmatrix / mma.sync)
// ---------------------------------------------------------------------------
__device__ __forceinline__ uint32_t smem_u32(const void* p){
    uint32_t a;
    asm("{ .reg .u64 t; cvta.to.shared.u64 t, %1; cvt.u32.u64 %0, t; }"
        : "=r"(a) : "l"(p));
    return a;
}
#define CPA(dst,src) \
    asm volatile("cp.async.cg.shared.global [%0], [%1], 16;" :: "r"(dst), "l"(src))
#define CPA_COMMIT() asm volatile("cp.async.commit_group;" ::: "memory")
#define CPA_WAIT(n)  asm volatile("cp.async.wait_group %0;" :: "n"(n) : "memory")

__device__ __forceinline__ void ldm_x4(uint32_t* r, uint32_t a){
    asm volatile("ldmatrix.sync.aligned.m8n8.x4.shared.b16 {%0,%1,%2,%3}, [%4];"
        : "=r"(r[0]), "=r"(r[1]), "=r"(r[2]), "=r"(r[3]) : "r"(a));
}
__device__ __forceinline__ void mma16(float* c, const uint32_t* a, const uint32_t* b){
    asm volatile("mma.sync.aligned.m16n8k16.row.col.f32.f16.f16.f32 "
        "{%0,%1,%2,%3}, {%4,%5,%6,%7}, {%8,%9}, {%0,%1,%2,%3};"
        : "+f"(c[0]), "+f"(c[1]), "+f"(c[2]), "+f"(c[3])
        : "r"(a[0]), "r"(a[1]), "r"(a[2]), "r"(a[3]), "r"(b[0]), "r"(b[1]));
}

// ---------------------------------------------------------------------------
// fp16 warp-MMA GEMM: CTA tile 128x128, BK=64, 3-stage cp.async pipeline.
// A: K-major [m][k] (lda elems).  Bt: K-major transposed-B [n][k] (ldb elems).
// MODE 0: fp32 store (proj)
// MODE 1: p = exp(v*0.125 - 8) -> fp16 store (fused scores+exp)
// MODE 2: accumulate A row-sums in-loop; epilogue: v /= rowsum -> fp16 (PV)
// smem: 3 stages x (A 16KB + B 16KB) = 96KB; 128B rows, XOR-16B swizzle.
// ---------------------------------------------------------------------------
template<int MODE, typename CT>
__device__ __forceinline__ void gemm_h(
    const __half* __restrict__ A,  int lda,
    const __half* __restrict__ Bt, int ldb,
    CT* __restrict__ C, int ldc,
    int K, int m0, int n0)
{
    extern __shared__ char sm[];
    const uint32_t sb = smem_u32(sm);
    const int tid = threadIdx.x, lane = tid & 31, wid = tid >> 5;
    const int wm = (wid & 1) * 64;      // warp grid 2 (M) x 4 (N): 64x32 per warp
    const int wn = (wid >> 1) * 32;

    // gmem->smem: 32 rows/pass (4 passes), 8x16B chunks per 128B row (64 halves)
    const int lrow = tid >> 3;
    const uint32_t lcb = (tid & 7) * 16;
    const __half* aptr = A  + (size_t)(m0 + lrow) * lda + (tid & 7) * 8;
    const __half* bptr = Bt + (size_t)(n0 + lrow) * ldb + (tid & 7) * 8;

    auto load_stage = [&](int stg, int k0){
        const uint32_t base = sb + stg * 32768;
        #pragma unroll
        for (int i = 0; i < 4; i++){
            const int r = lrow + 32 * i;
            const uint32_t d = base + r * 128 + (lcb ^ ((r & 7) << 4));
            CPA(d,         aptr + (size_t)(32 * i) * lda + k0);
            CPA(d + 16384, bptr + (size_t)(32 * i) * ldb + k0);
        }
        CPA_COMMIT();
    };

    // ldmatrix lane geometry (m16n8k16 fragments)
    const int arow = ((lane >> 3) & 1) * 8 + (lane & 7);   // A: m-half x k-half
    const uint32_t acb = ((lane >> 4) & 1) * 16;
    const int bnr  = ((lane >> 4) & 1) * 8 + (lane & 7);   // B: n-half x k-half
    const uint32_t bcb = ((lane >> 3) & 1) * 16;
    const uint32_t ax = (lane & 7) << 4;                   // XOR term (row&7)

    const int S = K >> 6;
    load_stage(0, 0);
    if (S > 1) load_stage(1, 64);

    float acc[4][4][4] = {};
    float rs[8];
    if (MODE == 2){
        #pragma unroll
        for (int i = 0; i < 8; i++) rs[i] = 0.f;
    }

    for (int s = 0; s < S; s++){
        if (s + 2 <= S) { CPA_WAIT(1); } else { CPA_WAIT(0); }
        __syncthreads();
        if (s + 2 < S) load_stage((s + 2) % 3, (s + 2) << 6);

        const uint32_t base = sb + (s % 3) * 32768;
        #pragma unroll
        for (int c = 0; c < 4; c++){               // 4 k-steps of 16 within BK=64
            uint32_t af[4][4], bf[2][4];
            #pragma unroll
            for (int mf = 0; mf < 4; mf++)
                ldm_x4(af[mf], base + (wm + mf*16 + arow) * 128
                                    + ((c*32 + acb) ^ ax));
            #pragma unroll
            for (int p = 0; p < 2; p++)
                ldm_x4(bf[p], base + 16384 + (wn + p*16 + bnr) * 128
                                    + ((c*32 + bcb) ^ ax));
            if (MODE == 2){
                // row-sum of A fragments (each warp spans full K row over loop)
                #pragma unroll
                for (int mf = 0; mf < 4; mf++){
                    __half2 s0 = __hadd2(*(const __half2*)&af[mf][0],
                                         *(const __half2*)&af[mf][2]);
                    __half2 s1 = __hadd2(*(const __half2*)&af[mf][1],
                                         *(const __half2*)&af[mf][3]);
                    float2 f0 = __half22float2(s0), f1 = __half22float2(s1);
                    rs[mf*2]   += f0.x + f0.y;
                    rs[mf*2+1] += f1.x + f1.y;
                }
            }
            #pragma unroll
            for (int mf = 0; mf < 4; mf++)
                #pragma unroll
                for (int nf = 0; nf < 4; nf++)
                    mma16(acc[mf][nf], af[mf], &bf[nf >> 1][(nf & 1) * 2]);
        }
    }

    float inv[8];
    if (MODE == 2){
        #pragma unroll
        for (int i = 0; i < 8; i++){
            rs[i] += __shfl_xor_sync(0xFFFFFFFFu, rs[i], 1);
            rs[i] += __shfl_xor_sync(0xFFFFFFFFu, rs[i], 2);
            inv[i] = __fdividef(1.f, rs[i]);
        }
    }

    // epilogue
    const int lr = lane >> 2, lc = (lane & 3) * 2;
    #pragma unroll
    for (int mf = 0; mf < 4; mf++){
        const int row = m0 + wm + mf * 16 + lr;
        #pragma unroll
        for (int nf = 0; nf < 4; nf++){
            const int col = n0 + wn + nf * 8 + lc;
            float v0 = acc[mf][nf][0], v1 = acc[mf][nf][1];
            float v2 = acc[mf][nf][2], v3 = acc[mf][nf][3];
            if (MODE == 1){
                v0 = __expf(fmaf(v0, 0.125f, -8.f));
                v1 = __expf(fmaf(v1, 0.125f, -8.f));
                v2 = __expf(fmaf(v2, 0.125f, -8.f));
                v3 = __expf(fmaf(v3, 0.125f, -8.f));
            }
            if (MODE == 2){
                v0 *= inv[mf*2];   v1 *= inv[mf*2];
                v2 *= inv[mf*2+1]; v3 *= inv[mf*2+1];
            }
            if (MODE == 0){
                float* Cf = (float*)C;
                *(float2*)&Cf[(size_t)row * ldc + col]       = make_float2(v0, v1);
                *(float2*)&Cf[(size_t)(row + 8) * ldc + col] = make_float2(v2, v3);
            } else {
                __half* Ch = (__half*)C;
                *(__half2*)&Ch[(size_t)row * ldc + col]       = __floats2half2_rn(v0, v1);
                *(__half2*)&Ch[(size_t)(row + 8) * ldc + col] = __floats2half2_rn(v2, v3);
            }
        }
    }
}

// ---------------------------------------------------------------------------
// GEMM kernels
// ---------------------------------------------------------------------------
__global__ __launch_bounds__(256) void scores_mma(){
    const int bh = blockIdx.z, b = bh >> 4, h = bh & 15;
    const __half* Ax = g_xh + (size_t)b * TT * CC + h * 64;
    gemm_h<1>(Ax, CC, Ax, CC,
              g_ph + (size_t)bh * TT * TT, TT,
              64, blockIdx.y * 128, blockIdx.x * 128);
}

__global__ __launch_bounds__(256) void pv_mma(){
    const int bh = blockIdx.z, b = bh >> 4, h = bh & 15;
    gemm_h<2>(g_ph + (size_t)bh * TT * TT, TT,
              g_xTh + (size_t)b * CC * TT, TT,
              g_oh + (size_t)b * TT * NHC + h * CC, NHC,
              TT, blockIdx.y * 128, blockIdx.x * 128);
}

__global__ __launch_bounds__(256) void proj_mma(float* __restrict__ out){
    gemm_h<0>(g_oh, NHC, g_wTh, NHC, out, CC,
              NHC, blockIdx.y * 128, blockIdx.x * 128);
}

// ---------------------------------------------------------------------------
// Prep: x -> fp16 (g_xh) + fp16 transpose (g_xTh); W -> fp16 transpose (g_wTh)
// ---------------------------------------------------------------------------
__global__ __launch_bounds__(256) void prep_x(const float* __restrict__ x){
    __shared__ float t[32][33];
    const int b = blockIdx.z;
    const int t0 = blockIdx.x * 32, c0 = blockIdx.y * 32;
    const int tx = threadIdx.x & 31, ty = threadIdx.x >> 5;
    #pragma unroll
    for (int i = 0; i < 4; i++){
        const int row = ty + 8 * i;
        const size_t idx = (size_t)b * TT * CC + (size_t)(t0 + row) * CC + c0 + tx;
        const float v = x[idx];
        g_xh[idx] = __float2half_rn(v);
        t[row][tx] = v;
    }
    __syncthreads();
    #pragma unroll
    for (int i = 0; i < 4; i++){
        const int row = ty + 8 * i;   // c index within tile
        g_xTh[(size_t)b * CC * TT + (size_t)(c0 + row) * TT + t0 + tx] =
            __float2half_rn(t[tx][row]);
    }
}

__global__ __launch_bounds__(256) void prep_w(const float* __restrict__ w){
    __shared__ float t[32][33];
    const int k0 = blockIdx.x * 32, n0 = blockIdx.y * 32;
    const int tx = threadIdx.x & 31, ty = threadIdx.x >> 5;
    #pragma unroll
    for (int i = 0; i < 4; i++){
        const int row = ty + 8 * i;
        t[row][tx] = w[(size_t)(k0 + row) * CC + n0 + tx];
    }
    __syncthreads();
    #pragma unroll
    for (int i = 0; i < 4; i++){
        const int row = ty + 8 * i;   // n index within tile
        g_wTh[(size_t)(n0 + row) * NHC + k0 + tx] = __float2half_rn(t[tx][row]);
    }
}

// ---------------------------------------------------------------------------
extern "C" void kernel_launch(void* const* d_in, const int* in_sizes, int n_in,
                              void* d_out, int out_size) {
    const float* x = (const float*)d_in[0];
    const float* w = (const float*)d_in[1];
    float* out = (float*)d_out;

    const int SMEM = 3 * 32768;   // 98304
    cudaFuncSetAttribute(scores_mma, cudaFuncAttributeMaxDynamicSharedMemorySize, SMEM);
    cudaFuncSetAttribute(pv_mma,     cudaFuncAttributeMaxDynamicSharedMemorySize, SMEM);
    cudaFuncSetAttribute(proj_mma,   cudaFuncAttributeMaxDynamicSharedMemorySize, SMEM);

    prep_x<<<dim3(TT/32, CC/32, BB), 256>>>(x);
    prep_w<<<dim3(NHC/32, CC/32), 256>>>(w);
    scores_mma<<<dim3(TT/128, TT/128, BB*NH), 256, SMEM>>>();
    pv_mma<<<dim3(CC/128, TT/128, BB*NH), 256, SMEM>>>();
    proj_mma<<<dim3(CC/128, (BB*TT)/128), 256, SMEM>>>(out);
}

// round 12
// speedup vs baseline: 1.1683x; 1.1683x over previous
#include <cuda_runtime.h>
#include <cuda_fp16.h>
#include <cstdint>

#define TT 2048
#define CC 1024
#define NH 16
#define BB 2
#define NHC (NH*CC)   // 16384

// ---- static device scratch (no allocation anywhere) ----
__device__ __align__(16) __half g_ph [(size_t)BB*NH*TT*TT];  // 256 MB fp16 unnorm P
__device__ __align__(16) __half g_oh [(size_t)BB*TT*NHC];    // 128 MB fp16 O
__device__ __align__(16) __half g_xh [(size_t)BB*TT*CC];     //   8 MB fp16 x
__device__ __align__(16) __half g_xTh[(size_t)BB*CC*TT];     //   8 MB fp16 x^T
__device__ __align__(16) __half g_wTh[(size_t)CC*NHC];       //  32 MB fp16 W^T
__device__ float g_inv[(size_t)BB*NH*TT];                    // 256 KB 1/rowsum

// ---------------------------------------------------------------------------
// helpers (family-wide PTX only: cp.async / ldmatrix / mma.sync)
// ---------------------------------------------------------------------------
__device__ __forceinline__ uint32_t smem_u32(const void* p){
    uint32_t a;
    asm("{ .reg .u64 t; cvta.to.shared.u64 t, %1; cvt.u32.u64 %0, t; }"
        : "=r"(a) : "l"(p));
    return a;
}
#define CPA(dst,src) \
    asm volatile("cp.async.cg.shared.global [%0], [%1], 16;" :: "r"(dst), "l"(src))
#define CPA_COMMIT() asm volatile("cp.async.commit_group;" ::: "memory")
#define CPA_WAIT(n)  asm volatile("cp.async.wait_group %0;" :: "n"(n) : "memory")

__device__ __forceinline__ void ldm_x4(uint32_t* r, uint32_t a){
    asm volatile("ldmatrix.sync.aligned.m8n8.x4.shared.b16 {%0,%1,%2,%3}, [%4];"
        : "=r"(r[0]), "=r"(r[1]), "=r"(r[2]), "=r"(r[3]) : "r"(a));
}
__device__ __forceinline__ void mma16(float* c, const uint32_t* a, const uint32_t* b){
    asm volatile("mma.sync.aligned.m16n8k16.row.col.f32.f16.f16.f32 "
        "{%0,%1,%2,%3}, {%4,%5,%6,%7}, {%8,%9}, {%0,%1,%2,%3};"
        : "+f"(c[0]), "+f"(c[1]), "+f"(c[2]), "+f"(c[3])
        : "r"(a[0]), "r"(a[1]), "r"(a[2]), "r"(a[3]), "r"(b[0]), "r"(b[1]));
}

// ---------------------------------------------------------------------------
// Scores GEMM: CTA 128x128, BK=64 (K=64 -> single iter), warp 64x32.
// Epilogue: p = exp(v*0.125 - 8) -> fp16.
// ---------------------------------------------------------------------------
__device__ __forceinline__ void gemm_scores(
    const __half* __restrict__ A, int lda,
    __half* __restrict__ C, int ldc,
    int m0, int n0)
{
    extern __shared__ char sm[];
    const uint32_t sb = smem_u32(sm);
    const int tid = threadIdx.x, lane = tid & 31, wid = tid >> 5;
    const int wm = (wid & 1) * 64;
    const int wn = (wid >> 1) * 32;

    const int lrow = tid >> 3;
    const uint32_t lcb = (tid & 7) * 16;
    const __half* aptr = A + (size_t)(m0 + lrow) * lda + (tid & 7) * 8;
    const __half* bptr = A + (size_t)(n0 + lrow) * lda + (tid & 7) * 8;

    #pragma unroll
    for (int i = 0; i < 4; i++){
        const int r = lrow + 32 * i;
        const uint32_t d = sb + r * 128 + (lcb ^ ((r & 7) << 4));
        CPA(d,         aptr + (size_t)(32 * i) * lda);
        CPA(d + 16384, bptr + (size_t)(32 * i) * lda);
    }
    CPA_COMMIT();

    const int arow = ((lane >> 3) & 1) * 8 + (lane & 7);
    const uint32_t acb = ((lane >> 4) & 1) * 16;
    const int bnr  = ((lane >> 4) & 1) * 8 + (lane & 7);
    const uint32_t bcb = ((lane >> 3) & 1) * 16;
    const uint32_t ax = (lane & 7) << 4;

    CPA_WAIT(0);
    __syncthreads();

    float acc[4][4][4] = {};
    #pragma unroll
    for (int c = 0; c < 4; c++){
        uint32_t af[4][4], bf[2][4];
        #pragma unroll
        for (int mf = 0; mf < 4; mf++)
            ldm_x4(af[mf], sb + (wm + mf*16 + arow) * 128 + ((c*32 + acb) ^ ax));
        #pragma unroll
        for (int p = 0; p < 2; p++)
            ldm_x4(bf[p], sb + 16384 + (wn + p*16 + bnr) * 128 + ((c*32 + bcb) ^ ax));
        #pragma unroll
        for (int mf = 0; mf < 4; mf++)
            #pragma unroll
            for (int nf = 0; nf < 4; nf++)
                mma16(acc[mf][nf], af[mf], &bf[nf >> 1][(nf & 1) * 2]);
    }

    const int lr = lane >> 2, lc = (lane & 3) * 2;
    #pragma unroll
    for (int mf = 0; mf < 4; mf++){
        const int row = m0 + wm + mf * 16 + lr;
        #pragma unroll
        for (int nf = 0; nf < 4; nf++){
            const int col = n0 + wn + nf * 8 + lc;
            float v0 = __expf(fmaf(acc[mf][nf][0], 0.125f, -8.f));
            float v1 = __expf(fmaf(acc[mf][nf][1], 0.125f, -8.f));
            float v2 = __expf(fmaf(acc[mf][nf][2], 0.125f, -8.f));
            float v3 = __expf(fmaf(acc[mf][nf][3], 0.125f, -8.f));
            *(__half2*)&C[(size_t)row * ldc + col]       = __floats2half2_rn(v0, v1);
            *(__half2*)&C[(size_t)(row + 8) * ldc + col] = __floats2half2_rn(v2, v3);
        }
    }
}

// ---------------------------------------------------------------------------
// Big GEMM: CTA 256x128, warp tile 64x64 (4M x 2N warps), BK=64, 3 stages.
// MODE 0: fp32 store (proj).  MODE 2: v *= invp[row], fp16 store (PV).
// smem/stage: A 32KB + B 16KB = 48KB; 3 stages = 144KB.
// ---------------------------------------------------------------------------
template<int MODE, typename CT>
__device__ __forceinline__ void gemm_big(
    const __half* __restrict__ A,  int lda,
    const __half* __restrict__ Bt, int ldb,
    CT* __restrict__ C, int ldc,
    int K, int m0, int n0, const float* __restrict__ invp)
{
    extern __shared__ char sm[];
    const uint32_t sb = smem_u32(sm);
    const int tid = threadIdx.x, lane = tid & 31, wid = tid >> 5;
    const int wm = (wid >> 1) * 64;     // 4 M groups
    const int wn = (wid & 1) * 64;      // 2 N groups
    constexpr int ASZ = 32768, STG = 49152;

    const int lrow = tid >> 3;
    const uint32_t lcb = (tid & 7) * 16;
    const __half* aptr = A  + (size_t)(m0 + lrow) * lda + (tid & 7) * 8;
    const __half* bptr = Bt + (size_t)(n0 + lrow) * ldb + (tid & 7) * 8;

    auto load_stage = [&](int stg, int k0){
        const uint32_t base = sb + stg * STG;
        #pragma unroll
        for (int i = 0; i < 8; i++){
            const int r = lrow + 32 * i;
            CPA(base + r * 128 + (lcb ^ ((r & 7) << 4)),
                aptr + (size_t)(32 * i) * lda + k0);
        }
        #pragma unroll
        for (int i = 0; i < 4; i++){
            const int r = lrow + 32 * i;
            CPA(base + ASZ + r * 128 + (lcb ^ ((r & 7) << 4)),
                bptr + (size_t)(32 * i) * ldb + k0);
        }
        CPA_COMMIT();
    };

    const int arow = ((lane >> 3) & 1) * 8 + (lane & 7);
    const uint32_t acb = ((lane >> 4) & 1) * 16;
    const int bnr  = ((lane >> 4) & 1) * 8 + (lane & 7);
    const uint32_t bcb = ((lane >> 3) & 1) * 16;
    const uint32_t ax = (lane & 7) << 4;

    const int S = K >> 6;
    load_stage(0, 0);
    load_stage(1, 64);

    float acc[4][8][4] = {};

    for (int s = 0; s < S; s++){
        if (s + 2 <= S) { CPA_WAIT(1); } else { CPA_WAIT(0); }
        __syncthreads();
        if (s + 2 < S) load_stage((s + 2) % 3, (s + 2) << 6);

        const uint32_t base = sb + (s % 3) * STG;
        #pragma unroll
        for (int c = 0; c < 4; c++){
            uint32_t af[4][4], bf[4][4];
            #pragma unroll
            for (int mf = 0; mf < 4; mf++)
                ldm_x4(af[mf], base + (wm + mf*16 + arow) * 128
                                    + ((c*32 + acb) ^ ax));
            #pragma unroll
            for (int p = 0; p < 4; p++)
                ldm_x4(bf[p], base + ASZ + (wn + p*16 + bnr) * 128
                                    + ((c*32 + bcb) ^ ax));
            #pragma unroll
            for (int mf = 0; mf < 4; mf++)
                #pragma unroll
                for (int nf = 0; nf < 8; nf++)
                    mma16(acc[mf][nf], af[mf], &bf[nf >> 1][(nf & 1) * 2]);
        }
    }

    // epilogue
    const int lr = lane >> 2, lc = (lane & 3) * 2;
    #pragma unroll
    for (int mf = 0; mf < 4; mf++){
        const int row = m0 + wm + mf * 16 + lr;
        float i0 = 1.f, i1 = 1.f;
        if (MODE == 2){ i0 = invp[row]; i1 = invp[row + 8]; }
        #pragma unroll
        for (int nf = 0; nf < 8; nf++){
            const int col = n0 + wn + nf * 8 + lc;
            float v0 = acc[mf][nf][0], v1 = acc[mf][nf][1];
            float v2 = acc[mf][nf][2], v3 = acc[mf][nf][3];
            if (MODE == 2){ v0 *= i0; v1 *= i0; v2 *= i1; v3 *= i1; }
            if (MODE == 0){
                float* Cf = (float*)C;
                *(float2*)&Cf[(size_t)row * ldc + col]       = make_float2(v0, v1);
                *(float2*)&Cf[(size_t)(row + 8) * ldc + col] = make_float2(v2, v3);
            } else {
                __half* Ch = (__half*)C;
                *(__half2*)&Ch[(size_t)row * ldc + col]       = __floats2half2_rn(v0, v1);
                *(__half2*)&Ch[(size_t)(row + 8) * ldc + col] = __floats2half2_rn(v2, v3);
            }
        }
    }
}

// ---------------------------------------------------------------------------
// Kernels
// ---------------------------------------------------------------------------
__global__ __launch_bounds__(256) void scores_mma(){
    const int bh = blockIdx.z, b = bh >> 4, h = bh & 15;
    const __half* Ax = g_xh + (size_t)b * TT * CC + h * 64;
    gemm_scores(Ax, CC, g_ph + (size_t)bh * TT * TT, TT,
                blockIdx.y * 128, blockIdx.x * 128);
}

// row sums of unnormalized P -> reciprocals. One block per row.
__global__ __launch_bounds__(256) void rowsum_kernel(){
    const size_t r = blockIdx.x;
    const __half* p = g_ph + r * TT;
    const int tid = threadIdx.x;
    __shared__ float red[8];

    uint4 u = *(const uint4*)&p[tid * 8];
    const __half2* h = (const __half2*)&u;
    float s = 0.f;
    #pragma unroll
    for (int j = 0; j < 4; j++){
        float2 f = __half22float2(h[j]);
        s += f.x + f.y;
    }
    #pragma unroll
    for (int o = 16; o; o >>= 1) s += __shfl_xor_sync(0xFFFFFFFFu, s, o);
    if ((tid & 31) == 0) red[tid >> 5] = s;
    __syncthreads();
    if (tid == 0){
        float t = red[0];
        #pragma unroll
        for (int i = 1; i < 8; i++) t += red[i];
        g_inv[r] = __fdividef(1.f, t);
    }
}

__global__ __launch_bounds__(256) void pv_mma(){
    const int bh = blockIdx.z, b = bh >> 4, h = bh & 15;
    gemm_big<2>(g_ph + (size_t)bh * TT * TT, TT,
                g_xTh + (size_t)b * CC * TT, TT,
                g_oh + (size_t)b * TT * NHC + h * CC, NHC,
                TT, blockIdx.y * 256, blockIdx.x * 128,
                g_inv + (size_t)bh * TT);
}

__global__ __launch_bounds__(256) void proj_mma(float* __restrict__ out){
    gemm_big<0>(g_oh, NHC, g_wTh, NHC, out, CC,
                NHC, blockIdx.y * 256, blockIdx.x * 128, (const float*)0);
}

// ---------------------------------------------------------------------------
// Prep: x -> fp16 (g_xh) + fp16 transpose (g_xTh); W -> fp16 transpose (g_wTh)
// ---------------------------------------------------------------------------
__global__ __launch_bounds__(256) void prep_x(const float* __restrict__ x){
    __shared__ float t[32][33];
    const int b = blockIdx.z;
    const int t0 = blockIdx.x * 32, c0 = blockIdx.y * 32;
    const int tx = threadIdx.x & 31, ty = threadIdx.x >> 5;
    #pragma unroll
    for (int i = 0; i < 4; i++){
        const int row = ty + 8 * i;
        const size_t idx = (size_t)b * TT * CC + (size_t)(t0 + row) * CC + c0 + tx;
        const float v = x[idx];
        g_xh[idx] = __float2half_rn(v);
        t[row][tx] = v;
    }
    __syncthreads();
    #pragma unroll
    for (int i = 0; i < 4; i++){
        const int row = ty + 8 * i;   // c index within tile
        g_xTh[(size_t)b * CC * TT + (size_t)(c0 + row) * TT + t0 + tx] =
            __float2half_rn(t[tx][row]);
    }
}

__global__ __launch_bounds__(256) void prep_w(const float* __restrict__ w){
    __shared__ float t[32][33];
    const int k0 = blockIdx.x * 32, n0 = blockIdx.y * 32;
    const int tx = threadIdx.x & 31, ty = threadIdx.x >> 5;
    #pragma unroll
    for (int i = 0; i < 4; i++){
        const int row = ty + 8 * i;
        t[row][tx] = w[(size_t)(k0 + row) * CC + n0 + tx];
    }
    __syncthreads();
    #pragma unroll
    for (int i = 0; i < 4; i++){
        const int row = ty + 8 * i;   // n index within tile
        g_wTh[(size_t)(n0 + row) * NHC + k0 + tx] = __float2half_rn(t[tx][row]);
    }
}

// ---------------------------------------------------------------------------
extern "C" void kernel_launch(void* const* d_in, const int* in_sizes, int n_in,
                              void* d_out, int out_size) {
    const float* x = (const float*)d_in[0];
    const float* w = (const float*)d_in[1];
    float* out = (float*)d_out;

    const int SMEM_S = 32768;         // scores: single stage A+B
    const int SMEM_B = 3 * 49152;     // big: 147456
    cudaFuncSetAttribute(scores_mma, cudaFuncAttributeMaxDynamicSharedMemorySize, SMEM_S);
    cudaFuncSetAttribute(pv_mma,     cudaFuncAttributeMaxDynamicSharedMemorySize, SMEM_B);
    cudaFuncSetAttribute(proj_mma,   cudaFuncAttributeMaxDynamicSharedMemorySize, SMEM_B);

    prep_x<<<dim3(TT/32, CC/32, BB), 256>>>(x);
    prep_w<<<dim3(NHC/32, CC/32), 256>>>(w);
    scores_mma<<<dim3(TT/128, TT/128, BB*NH), 256, SMEM_S>>>();
    rowsum_kernel<<<BB*NH*TT, 256>>>();
    pv_mma<<<dim3(CC/128, TT/256, BB*NH), 256, SMEM_B>>>();
    proj_mma<<<dim3(CC/128, (BB*TT)/256), 256, SMEM_B>>>(out);
}

// round 14
// speedup vs baseline: 1.3248x; 1.1340x over previous
#include <cuda_runtime.h>
#include <cuda_fp16.h>
#include <cstdint>

#define TT 2048
#define CC 1024
#define NH 16
#define BB 2
#define NHC (NH*CC)   // 16384

// ---- static device scratch (no allocation anywhere) ----
__device__ __align__(16) __half g_ph [(size_t)BB*NH*TT*TT];  // 256 MB fp16 unnorm P
__device__ __align__(16) __half g_oh [(size_t)BB*TT*NHC];    // 128 MB fp16 O
__device__ __align__(16) __half g_xh [(size_t)BB*TT*CC];     //   8 MB fp16 x
__device__ __align__(16) __half g_xTh[(size_t)BB*CC*TT];     //   8 MB fp16 x^T
__device__ __align__(16) __half g_wTh[(size_t)CC*NHC];       //  32 MB fp16 W^T
__device__ float g_sum[(size_t)BB*NH*TT];                    // 256 KB row sums

// ---------------------------------------------------------------------------
// helpers (family-wide PTX only: cp.async / ldmatrix / mma.sync)
// ---------------------------------------------------------------------------
__device__ __forceinline__ uint32_t smem_u32(const void* p){
    uint32_t a;
    asm("{ .reg .u64 t; cvta.to.shared.u64 t, %1; cvt.u32.u64 %0, t; }"
        : "=r"(a) : "l"(p));
    return a;
}
#define CPA(dst,src) \
    asm volatile("cp.async.cg.shared.global [%0], [%1], 16;" :: "r"(dst), "l"(src))
#define CPA_COMMIT() asm volatile("cp.async.commit_group;" ::: "memory")
#define CPA_WAIT(n)  asm volatile("cp.async.wait_group %0;" :: "n"(n) : "memory")

__device__ __forceinline__ void ldm_x4(uint32_t* r, uint32_t a){
    asm volatile("ldmatrix.sync.aligned.m8n8.x4.shared.b16 {%0,%1,%2,%3}, [%4];"
        : "=r"(r[0]), "=r"(r[1]), "=r"(r[2]), "=r"(r[3]) : "r"(a));
}
__device__ __forceinline__ void mma16(float* c, const uint32_t* a, const uint32_t* b){
    asm volatile("mma.sync.aligned.m16n8k16.row.col.f32.f16.f16.f32 "
        "{%0,%1,%2,%3}, {%4,%5,%6,%7}, {%8,%9}, {%0,%1,%2,%3};"
        : "+f"(c[0]), "+f"(c[1]), "+f"(c[2]), "+f"(c[3])
        : "r"(a[0]), "r"(a[1]), "r"(a[2]), "r"(a[3]), "r"(b[0]), "r"(b[1]));
}

// ---------------------------------------------------------------------------
// Scores GEMM: CTA 128x128, K=64 single pass, warp 64x32.
// Epilogue: p = exp(v*0.125 - 8) -> fp16; per-row partial sums -> atomicAdd.
// ---------------------------------------------------------------------------
__device__ __forceinline__ void gemm_scores(
    const __half* __restrict__ A, int lda,
    __half* __restrict__ C, int ldc,
    float* __restrict__ sum,
    int m0, int n0)
{
    extern __shared__ char sm[];
    const uint32_t sb = smem_u32(sm);
    const int tid = threadIdx.x, lane = tid & 31, wid = tid >> 5;
    const int wm = (wid & 1) * 64;
    const int wn = (wid >> 1) * 32;

    const int lrow = tid >> 3;
    const uint32_t lcb = (tid & 7) * 16;
    const __half* aptr = A + (size_t)(m0 + lrow) * lda + (tid & 7) * 8;
    const __half* bptr = A + (size_t)(n0 + lrow) * lda + (tid & 7) * 8;

    #pragma unroll
    for (int i = 0; i < 4; i++){
        const int r = lrow + 32 * i;
        const uint32_t d = sb + r * 128 + (lcb ^ ((r & 7) << 4));
        CPA(d,         aptr + (size_t)(32 * i) * lda);
        CPA(d + 16384, bptr + (size_t)(32 * i) * lda);
    }
    CPA_COMMIT();

    const int arow = ((lane >> 3) & 1) * 8 + (lane & 7);
    const uint32_t acb = ((lane >> 4) & 1) * 16;
    const int bnr  = ((lane >> 4) & 1) * 8 + (lane & 7);
    const uint32_t bcb = ((lane >> 3) & 1) * 16;
    const uint32_t ax = (lane & 7) << 4;

    CPA_WAIT(0);
    __syncthreads();

    float acc[4][4][4] = {};
    #pragma unroll
    for (int c = 0; c < 4; c++){
        uint32_t af[4][4], bf[2][4];
        #pragma unroll
        for (int mf = 0; mf < 4; mf++)
            ldm_x4(af[mf], sb + (wm + mf*16 + arow) * 128 + ((c*32 + acb) ^ ax));
        #pragma unroll
        for (int p = 0; p < 2; p++)
            ldm_x4(bf[p], sb + 16384 + (wn + p*16 + bnr) * 128 + ((c*32 + bcb) ^ ax));
        #pragma unroll
        for (int mf = 0; mf < 4; mf++)
            #pragma unroll
            for (int nf = 0; nf < 4; nf++)
                mma16(acc[mf][nf], af[mf], &bf[nf >> 1][(nf & 1) * 2]);
    }

    const int lr = lane >> 2, lc = (lane & 3) * 2;
    #pragma unroll
    for (int mf = 0; mf < 4; mf++){
        const int row = m0 + wm + mf * 16 + lr;
        float rs0 = 0.f, rs1 = 0.f;
        #pragma unroll
        for (int nf = 0; nf < 4; nf++){
            const int col = n0 + wn + nf * 8 + lc;
            float v0 = __expf(fmaf(acc[mf][nf][0], 0.125f, -8.f));
            float v1 = __expf(fmaf(acc[mf][nf][1], 0.125f, -8.f));
            float v2 = __expf(fmaf(acc[mf][nf][2], 0.125f, -8.f));
            float v3 = __expf(fmaf(acc[mf][nf][3], 0.125f, -8.f));
            rs0 += v0 + v1;
            rs1 += v2 + v3;
            *(__half2*)&C[(size_t)row * ldc + col]       = __floats2half2_rn(v0, v1);
            *(__half2*)&C[(size_t)(row + 8) * ldc + col] = __floats2half2_rn(v2, v3);
        }
        rs0 += __shfl_xor_sync(0xFFFFFFFFu, rs0, 1);
        rs0 += __shfl_xor_sync(0xFFFFFFFFu, rs0, 2);
        rs1 += __shfl_xor_sync(0xFFFFFFFFu, rs1, 1);
        rs1 += __shfl_xor_sync(0xFFFFFFFFu, rs1, 2);
        if ((lane & 3) == 0){
            atomicAdd(&sum[row], rs0);
            atomicAdd(&sum[row + 8], rs1);
        }
    }
}

// ---------------------------------------------------------------------------
// Main GEMM: CTA 128x128, warp 64x32 (2M x 4N), BK=64, 3 stages, 2 CTAs/SM.
// MODE 0: fp32 store (proj).  MODE 2: v *= 1/sum[row], fp16 store (PV).
// ---------------------------------------------------------------------------
template<int MODE, typename CT>
__device__ __forceinline__ void gemm128(
    const __half* __restrict__ A,  int lda,
    const __half* __restrict__ Bt, int ldb,
    CT* __restrict__ C, int ldc,
    int K, int m0, int n0, const float* __restrict__ sump)
{
    extern __shared__ char sm[];
    const uint32_t sb = smem_u32(sm);
    const int tid = threadIdx.x, lane = tid & 31, wid = tid >> 5;
    const int wm = (wid & 1) * 64;
    const int wn = (wid >> 1) * 32;

    const int lrow = tid >> 3;
    const uint32_t lcb = (tid & 7) * 16;
    const __half* aptr = A  + (size_t)(m0 + lrow) * lda + (tid & 7) * 8;
    const __half* bptr = Bt + (size_t)(n0 + lrow) * ldb + (tid & 7) * 8;

    auto load_stage = [&](int stg, int k0){
        const uint32_t base = sb + stg * 32768;
        #pragma unroll
        for (int i = 0; i < 4; i++){
            const int r = lrow + 32 * i;
            const uint32_t d = base + r * 128 + (lcb ^ ((r & 7) << 4));
            CPA(d,         aptr + (size_t)(32 * i) * lda + k0);
            CPA(d + 16384, bptr + (size_t)(32 * i) * ldb + k0);
        }
        CPA_COMMIT();
    };

    const int arow = ((lane >> 3) & 1) * 8 + (lane & 7);
    const uint32_t acb = ((lane >> 4) & 1) * 16;
    const int bnr  = ((lane >> 4) & 1) * 8 + (lane & 7);
    const uint32_t bcb = ((lane >> 3) & 1) * 16;
    const uint32_t ax = (lane & 7) << 4;

    const int S = K >> 6;
    load_stage(0, 0);
    load_stage(1, 64);

    float acc[4][4][4] = {};

    for (int s = 0; s < S; s++){
        if (s + 2 <= S) { CPA_WAIT(1); } else { CPA_WAIT(0); }
        __syncthreads();
        if (s + 2 < S) load_stage((s + 2) % 3, (s + 2) << 6);

        const uint32_t base = sb + (s % 3) * 32768;
        #pragma unroll
        for (int c = 0; c < 4; c++){
            uint32_t af[4][4], bf[2][4];
            #pragma unroll
            for (int mf = 0; mf < 4; mf++)
                ldm_x4(af[mf], base + (wm + mf*16 + arow) * 128
                                    + ((c*32 + acb) ^ ax));
            #pragma unroll
            for (int p = 0; p < 2; p++)
                ldm_x4(bf[p], base + 16384 + (wn + p*16 + bnr) * 128
                                    + ((c*32 + bcb) ^ ax));
            #pragma unroll
            for (int mf = 0; mf < 4; mf++)
                #pragma unroll
                for (int nf = 0; nf < 4; nf++)
                    mma16(acc[mf][nf], af[mf], &bf[nf >> 1][(nf & 1) * 2]);
        }
    }

    // epilogue
    const int lr = lane >> 2, lc = (lane & 3) * 2;
    #pragma unroll
    for (int mf = 0; mf < 4; mf++){
        const int row = m0 + wm + mf * 16 + lr;
        float i0 = 1.f, i1 = 1.f;
        if (MODE == 2){
            i0 = __fdividef(1.f, sump[row]);
            i1 = __fdividef(1.f, sump[row + 8]);
        }
        #pragma unroll
        for (int nf = 0; nf < 4; nf++){
            const int col = n0 + wn + nf * 8 + lc;
            float v0 = acc[mf][nf][0], v1 = acc[mf][nf][1];
            float v2 = acc[mf][nf][2], v3 = acc[mf][nf][3];
            if (MODE == 2){ v0 *= i0; v1 *= i0; v2 *= i1; v3 *= i1; }
            if (MODE == 0){
                float* Cf = (float*)C;
                *(float2*)&Cf[(size_t)row * ldc + col]       = make_float2(v0, v1);
                *(float2*)&Cf[(size_t)(row + 8) * ldc + col] = make_float2(v2, v3);
            } else {
                __half* Ch = (__half*)C;
                *(__half2*)&Ch[(size_t)row * ldc + col]       = __floats2half2_rn(v0, v1);
                *(__half2*)&Ch[(size_t)(row + 8) * ldc + col] = __floats2half2_rn(v2, v3);
            }
        }
    }
}

// ---------------------------------------------------------------------------
// Kernels
// ---------------------------------------------------------------------------
__global__ __launch_bounds__(256) void zero_sum(){
    g_sum[blockIdx.x * 256 + threadIdx.x] = 0.f;
}

__global__ __launch_bounds__(256) void scores_mma(){
    const int bh = blockIdx.z, b = bh >> 4, h = bh & 15;
    const __half* Ax = g_xh + (size_t)b * TT * CC + h * 64;
    gemm_scores(Ax, CC, g_ph + (size_t)bh * TT * TT, TT,
                g_sum + (size_t)bh * TT,
                blockIdx.y * 128, blockIdx.x * 128);
}

__global__ __launch_bounds__(256, 2) void pv_mma(){
    const int bh = blockIdx.z, b = bh >> 4, h = bh & 15;
    gemm128<2>(g_ph + (size_t)bh * TT * TT, TT,
               g_xTh + (size_t)b * CC * TT, TT,
               g_oh + (size_t)b * TT * NHC + h * CC, NHC,
               TT, blockIdx.y * 128, blockIdx.x * 128,
               g_sum + (size_t)bh * TT);
}

__global__ __launch_bounds__(256, 2) void proj_mma(float* __restrict__ out){
    gemm128<0>(g_oh, NHC, g_wTh, NHC, out, CC,
               NHC, blockIdx.y * 128, blockIdx.x * 128, (const float*)0);
}

// ---------------------------------------------------------------------------
// Prep: x -> fp16 (g_xh) + fp16 transpose (g_xTh); W -> fp16 transpose (g_wTh)
// ---------------------------------------------------------------------------
__global__ __launch_bounds__(256) void prep_x(const float* __restrict__ x){
    __shared__ float t[32][33];
    const int b = blockIdx.z;
    const int t0 = blockIdx.x * 32, c0 = blockIdx.y * 32;
    const int tx = threadIdx.x & 31, ty = threadIdx.x >> 5;
    #pragma unroll
    for (int i = 0; i < 4; i++){
        const int row = ty + 8 * i;
        const size_t idx = (size_t)b * TT * CC + (size_t)(t0 + row) * CC + c0 + tx;
        const float v = x[idx];
        g_xh[idx] = __float2half_rn(v);
        t[row][tx] = v;
    }
    __syncthreads();
    #pragma unroll
    for (int i = 0; i < 4; i++){
        const int row = ty + 8 * i;   // c index within tile
        g_xTh[(size_t)b * CC * TT + (size_t)(c0 + row) * TT + t0 + tx] =
            __float2half_rn(t[tx][row]);
    }
}

__global__ __launch_bounds__(256) void prep_w(const float* __restrict__ w){
    __shared__ float t[32][33];
    const int k0 = blockIdx.x * 32, n0 = blockIdx.y * 32;
    const int tx = threadIdx.x & 31, ty = threadIdx.x >> 5;
    #pragma unroll
    for (int i = 0; i < 4; i++){
        const int row = ty + 8 * i;
        t[row][tx] = w[(size_t)(k0 + row) * CC + n0 + tx];
    }
    __syncthreads();
    #pragma unroll
    for (int i = 0; i < 4; i++){
        const int row = ty + 8 * i;   // n index within tile
        g_wTh[(size_t)(n0 + row) * NHC + k0 + tx] = __float2half_rn(t[tx][row]);
    }
}

// ---------------------------------------------------------------------------
extern "C" void kernel_launch(void* const* d_in, const int* in_sizes, int n_in,
                              void* d_out, int out_size) {
    const float* x = (const float*)d_in[0];
    const float* w = (const float*)d_in[1];
    float* out = (float*)d_out;

    const int SMEM_S = 32768;       // scores: single stage A+B
    const int SMEM_G = 3 * 32768;   // pipelined GEMMs: 96 KB
    cudaFuncSetAttribute(scores_mma, cudaFuncAttributeMaxDynamicSharedMemorySize, SMEM_S);
    cudaFuncSetAttribute(pv_mma,     cudaFuncAttributeMaxDynamicSharedMemorySize, SMEM_G);
    cudaFuncSetAttribute(proj_mma,   cudaFuncAttributeMaxDynamicSharedMemorySize, SMEM_G);

    zero_sum<<<(BB*NH*TT)/256, 256>>>();
    prep_x<<<dim3(TT/32, CC/32, BB), 256>>>(x);
    prep_w<<<dim3(NHC/32, CC/32), 256>>>(w);
    scores_mma<<<dim3(TT/128, TT/128, BB*NH), 256, SMEM_S>>>();
    pv_mma<<<dim3(CC/128, TT/128, BB*NH), 256, SMEM_G>>>();
    proj_mma<<<dim3(CC/128, (BB*TT)/128), 256, SMEM_G>>>(out);
}

// round 15
// speedup vs baseline: 1.3354x; 1.0080x over previous
#include <cuda_runtime.h>
#include <cuda_fp16.h>
#include <cstdint>

#define TT 2048
#define CC 1024
#define NH 16
#define BB 2
#define NHC (NH*CC)   // 16384

// ---- static device scratch (no allocation anywhere) ----
__device__ __align__(16) __half g_ph [(size_t)BB*NH*TT*TT];  // 256 MB fp16 unnorm P
__device__ __align__(16) __half g_oh [(size_t)BB*TT*NHC];    // 128 MB fp16 O
__device__ __align__(16) __half g_xh [(size_t)BB*TT*CC];     //   8 MB fp16 x
__device__ __align__(16) __half g_xTh[(size_t)BB*CC*TT];     //   8 MB fp16 x^T
__device__ __align__(16) __half g_wTh[(size_t)CC*NHC];       //  32 MB fp16 W^T
__device__ float g_sum[(size_t)BB*NH*TT];                    // 256 KB row sums

// ---------------------------------------------------------------------------
// helpers (family-wide PTX only: cp.async / ldmatrix / mma.sync)
// ---------------------------------------------------------------------------
__device__ __forceinline__ uint32_t smem_u32(const void* p){
    uint32_t a;
    asm("{ .reg .u64 t; cvta.to.shared.u64 t, %1; cvt.u32.u64 %0, t; }"
        : "=r"(a) : "l"(p));
    return a;
}
#define CPA(dst,src) \
    asm volatile("cp.async.cg.shared.global [%0], [%1], 16;" :: "r"(dst), "l"(src))
#define CPA_COMMIT() asm volatile("cp.async.commit_group;" ::: "memory")
#define CPA_WAIT(n)  asm volatile("cp.async.wait_group %0;" :: "n"(n) : "memory")

__device__ __forceinline__ void ldm_x4(uint32_t* r, uint32_t a){
    asm volatile("ldmatrix.sync.aligned.m8n8.x4.shared.b16 {%0,%1,%2,%3}, [%4];"
        : "=r"(r[0]), "=r"(r[1]), "=r"(r[2]), "=r"(r[3]) : "r"(a));
}
__device__ __forceinline__ void mma16(float* c, const uint32_t* a, const uint32_t* b){
    asm volatile("mma.sync.aligned.m16n8k16.row.col.f32.f16.f16.f32 "
        "{%0,%1,%2,%3}, {%4,%5,%6,%7}, {%8,%9}, {%0,%1,%2,%3};"
        : "+f"(c[0]), "+f"(c[1]), "+f"(c[2]), "+f"(c[3])
        : "r"(a[0]), "r"(a[1]), "r"(a[2]), "r"(a[3]), "r"(b[0]), "r"(b[1]));
}

// ---------------------------------------------------------------------------
// Scores GEMM: CTA strip 128x512, K=64. A tile loaded ONCE (16KB),
// 4 B sub-tiles (128x64) streamed through a 2-buffer cp.async pipeline.
// Epilogue: p = exp(v*0.125 - 8) -> fp16; row sums accumulated across the
// 4 sub-tiles in regs, single atomicAdd per row at the end.
// smem: A 16KB + 2x B 16KB = 48KB.
// ---------------------------------------------------------------------------
__device__ __forceinline__ void gemm_scores(
    const __half* __restrict__ A, int lda,
    __half* __restrict__ C, int ldc,
    float* __restrict__ sum,
    int m0, int n0base)
{
    extern __shared__ char sm[];
    const uint32_t sb = smem_u32(sm);
    const int tid = threadIdx.x, lane = tid & 31, wid = tid >> 5;
    const int wm = (wid & 1) * 64;
    const int wn = (wid >> 1) * 32;

    const int lrow = tid >> 3;
    const uint32_t lcb = (tid & 7) * 16;
    const __half* aptr = A + (size_t)(m0 + lrow) * lda + (tid & 7) * 8;

    auto load_b = [&](int nt, int buf){
        const __half* bptr = A + (size_t)(n0base + nt * 128 + lrow) * lda
                               + (tid & 7) * 8;
        const uint32_t bb = sb + 16384 + buf * 16384;
        #pragma unroll
        for (int i = 0; i < 4; i++){
            const int r = lrow + 32 * i;
            CPA(bb + r * 128 + (lcb ^ ((r & 7) << 4)),
                bptr + (size_t)(32 * i) * lda);
        }
        CPA_COMMIT();
    };

    // G0 = A tile + B0, G1 = B1
    #pragma unroll
    for (int i = 0; i < 4; i++){
        const int r = lrow + 32 * i;
        CPA(sb + r * 128 + (lcb ^ ((r & 7) << 4)),
            aptr + (size_t)(32 * i) * lda);
    }
    {
        const __half* bptr = A + (size_t)(n0base + lrow) * lda + (tid & 7) * 8;
        #pragma unroll
        for (int i = 0; i < 4; i++){
            const int r = lrow + 32 * i;
            CPA(sb + 16384 + r * 128 + (lcb ^ ((r & 7) << 4)),
                bptr + (size_t)(32 * i) * lda);
        }
        CPA_COMMIT();
    }
    load_b(1, 1);

    const int arow = ((lane >> 3) & 1) * 8 + (lane & 7);
    const uint32_t acb = ((lane >> 4) & 1) * 16;
    const int bnr  = ((lane >> 4) & 1) * 8 + (lane & 7);
    const uint32_t bcb = ((lane >> 3) & 1) * 16;
    const uint32_t ax = (lane & 7) << 4;
    const int lr = lane >> 2, lc = (lane & 3) * 2;

    float rs[4][2];
    #pragma unroll
    for (int mf = 0; mf < 4; mf++){ rs[mf][0] = 0.f; rs[mf][1] = 0.f; }

    #pragma unroll
    for (int nt = 0; nt < 4; nt++){
        if (nt < 3) { CPA_WAIT(1); } else { CPA_WAIT(0); }
        __syncthreads();

        const uint32_t bb = sb + 16384 + (nt & 1) * 16384;
        float acc[4][4][4] = {};
        #pragma unroll
        for (int c = 0; c < 4; c++){
            uint32_t af[4][4], bf[2][4];
            #pragma unroll
            for (int mf = 0; mf < 4; mf++)
                ldm_x4(af[mf], sb + (wm + mf*16 + arow) * 128
                                  + ((c*32 + acb) ^ ax));
            #pragma unroll
            for (int p = 0; p < 2; p++)
                ldm_x4(bf[p], bb + (wn + p*16 + bnr) * 128
                                  + ((c*32 + bcb) ^ ax));
            #pragma unroll
            for (int mf = 0; mf < 4; mf++)
                #pragma unroll
                for (int nf = 0; nf < 4; nf++)
                    mma16(acc[mf][nf], af[mf], &bf[nf >> 1][(nf & 1) * 2]);
        }

        // epilogue for this sub-tile
        #pragma unroll
        for (int mf = 0; mf < 4; mf++){
            const int row = m0 + wm + mf * 16 + lr;
            #pragma unroll
            for (int nf = 0; nf < 4; nf++){
                const int col = n0base + nt * 128 + wn + nf * 8 + lc;
                float v0 = __expf(fmaf(acc[mf][nf][0], 0.125f, -8.f));
                float v1 = __expf(fmaf(acc[mf][nf][1], 0.125f, -8.f));
                float v2 = __expf(fmaf(acc[mf][nf][2], 0.125f, -8.f));
                float v3 = __expf(fmaf(acc[mf][nf][3], 0.125f, -8.f));
                rs[mf][0] += v0 + v1;
                rs[mf][1] += v2 + v3;
                *(__half2*)&C[(size_t)row * ldc + col]       = __floats2half2_rn(v0, v1);
                *(__half2*)&C[(size_t)(row + 8) * ldc + col] = __floats2half2_rn(v2, v3);
            }
        }
        __syncthreads();                 // all warps done with buffer (nt&1)
        if (nt + 2 < 4) load_b(nt + 2, nt & 1);
    }

    // final row-sum reduction + atomics (once per CTA)
    #pragma unroll
    for (int mf = 0; mf < 4; mf++){
        float r0 = rs[mf][0], r1 = rs[mf][1];
        r0 += __shfl_xor_sync(0xFFFFFFFFu, r0, 1);
        r0 += __shfl_xor_sync(0xFFFFFFFFu, r0, 2);
        r1 += __shfl_xor_sync(0xFFFFFFFFu, r1, 1);
        r1 += __shfl_xor_sync(0xFFFFFFFFu, r1, 2);
        if ((lane & 3) == 0){
            const int row = m0 + wm + mf * 16 + lr;
            atomicAdd(&sum[row], r0);
            atomicAdd(&sum[row + 8], r1);
        }
    }
}

// ---------------------------------------------------------------------------
// Main GEMM: CTA 128x128, warp 64x32 (2M x 4N), BK=64, 3 stages, 2 CTAs/SM.
// MODE 0: fp32 store (proj).  MODE 2: v *= 1/sum[row], fp16 store (PV).
// ---------------------------------------------------------------------------
template<int MODE, typename CT>
__device__ __forceinline__ void gemm128(
    const __half* __restrict__ A,  int lda,
    const __half* __restrict__ Bt, int ldb,
    CT* __restrict__ C, int ldc,
    int K, int m0, int n0, const float* __restrict__ sump)
{
    extern __shared__ char sm[];
    const uint32_t sb = smem_u32(sm);
    const int tid = threadIdx.x, lane = tid & 31, wid = tid >> 5;
    const int wm = (wid & 1) * 64;
    const int wn = (wid >> 1) * 32;

    const int lrow = tid >> 3;
    const uint32_t lcb = (tid & 7) * 16;
    const __half* aptr = A  + (size_t)(m0 + lrow) * lda + (tid & 7) * 8;
    const __half* bptr = Bt + (size_t)(n0 + lrow) * ldb + (tid & 7) * 8;

    auto load_stage = [&](int stg, int k0){
        const uint32_t base = sb + stg * 32768;
        #pragma unroll
        for (int i = 0; i < 4; i++){
            const int r = lrow + 32 * i;
            const uint32_t d = base + r * 128 + (lcb ^ ((r & 7) << 4));
            CPA(d,         aptr + (size_t)(32 * i) * lda + k0);
            CPA(d + 16384, bptr + (size_t)(32 * i) * ldb + k0);
        }
        CPA_COMMIT();
    };

    const int arow = ((lane >> 3) & 1) * 8 + (lane & 7);
    const uint32_t acb = ((lane >> 4) & 1) * 16;
    const int bnr  = ((lane >> 4) & 1) * 8 + (lane & 7);
    const uint32_t bcb = ((lane >> 3) & 1) * 16;
    const uint32_t ax = (lane & 7) << 4;

    const int S = K >> 6;
    load_stage(0, 0);
    load_stage(1, 64);

    float acc[4][4][4] = {};

    for (int s = 0; s < S; s++){
        if (s + 2 <= S) { CPA_WAIT(1); } else { CPA_WAIT(0); }
        __syncthreads();
        if (s + 2 < S) load_stage((s + 2) % 3, (s + 2) << 6);

        const uint32_t base = sb + (s % 3) * 32768;
        #pragma unroll
        for (int c = 0; c < 4; c++){
            uint32_t af[4][4], bf[2][4];
            #pragma unroll
            for (int mf = 0; mf < 4; mf++)
                ldm_x4(af[mf], base + (wm + mf*16 + arow) * 128
                                    + ((c*32 + acb) ^ ax));
            #pragma unroll
            for (int p = 0; p < 2; p++)
                ldm_x4(bf[p], base + 16384 + (wn + p*16 + bnr) * 128
                                    + ((c*32 + bcb) ^ ax));
            #pragma unroll
            for (int mf = 0; mf < 4; mf++)
                #pragma unroll
                for (int nf = 0; nf < 4; nf++)
                    mma16(acc[mf][nf], af[mf], &bf[nf >> 1][(nf & 1) * 2]);
        }
    }

    // epilogue
    const int lr = lane >> 2, lc = (lane & 3) * 2;
    #pragma unroll
    for (int mf = 0; mf < 4; mf++){
        const int row = m0 + wm + mf * 16 + lr;
        float i0 = 1.f, i1 = 1.f;
        if (MODE == 2){
            i0 = __fdividef(1.f, sump[row]);
            i1 = __fdividef(1.f, sump[row + 8]);
        }
        #pragma unroll
        for (int nf = 0; nf < 4; nf++){
            const int col = n0 + wn + nf * 8 + lc;
            float v0 = acc[mf][nf][0], v1 = acc[mf][nf][1];
            float v2 = acc[mf][nf][2], v3 = acc[mf][nf][3];
            if (MODE == 2){ v0 *= i0; v1 *= i0; v2 *= i1; v3 *= i1; }
            if (MODE == 0){
                float* Cf = (float*)C;
                *(float2*)&Cf[(size_t)row * ldc + col]       = make_float2(v0, v1);
                *(float2*)&Cf[(size_t)(row + 8) * ldc + col] = make_float2(v2, v3);
            } else {
                __half* Ch = (__half*)C;
                *(__half2*)&Ch[(size_t)row * ldc + col]       = __floats2half2_rn(v0, v1);
                *(__half2*)&Ch[(size_t)(row + 8) * ldc + col] = __floats2half2_rn(v2, v3);
            }
        }
    }
}

// ---------------------------------------------------------------------------
// Kernels
// ---------------------------------------------------------------------------
__global__ __launch_bounds__(256) void zero_sum(){
    g_sum[blockIdx.x * 256 + threadIdx.x] = 0.f;
}

__global__ __launch_bounds__(256, 2) void scores_mma(){
    const int bh = blockIdx.z, b = bh >> 4, h = bh & 15;
    const __half* Ax = g_xh + (size_t)b * TT * CC + h * 64;
    gemm_scores(Ax, CC, g_ph + (size_t)bh * TT * TT, TT,
                g_sum + (size_t)bh * TT,
                blockIdx.y * 128, blockIdx.x * 512);
}

__global__ __launch_bounds__(256, 2) void pv_mma(){
    const int bh = blockIdx.z, b = bh >> 4, h = bh & 15;
    gemm128<2>(g_ph + (size_t)bh * TT * TT, TT,
               g_xTh + (size_t)b * CC * TT, TT,
               g_oh + (size_t)b * TT * NHC + h * CC, NHC,
               TT, blockIdx.y * 128, blockIdx.x * 128,
               g_sum + (size_t)bh * TT);
}

__global__ __launch_bounds__(256, 2) void proj_mma(float* __restrict__ out){
    gemm128<0>(g_oh, NHC, g_wTh, NHC, out, CC,
               NHC, blockIdx.y * 128, blockIdx.x * 128, (const float*)0);
}

// ---------------------------------------------------------------------------
// Prep: x -> fp16 (g_xh) + fp16 transpose (g_xTh); W -> fp16 transpose (g_wTh)
// ---------------------------------------------------------------------------
__global__ __launch_bounds__(256) void prep_x(const float* __restrict__ x){
    __shared__ float t[32][33];
    const int b = blockIdx.z;
    const int t0 = blockIdx.x * 32, c0 = blockIdx.y * 32;
    const int tx = threadIdx.x & 31, ty = threadIdx.x >> 5;
    #pragma unroll
    for (int i = 0; i < 4; i++){
        const int row = ty + 8 * i;
        const size_t idx = (size_t)b * TT * CC + (size_t)(t0 + row) * CC + c0 + tx;
        const float v = x[idx];
        g_xh[idx] = __float2half_rn(v);
        t[row][tx] = v;
    }
    __syncthreads();
    #pragma unroll
    for (int i = 0; i < 4; i++){
        const int row = ty + 8 * i;   // c index within tile
        g_xTh[(size_t)b * CC * TT + (size_t)(c0 + row) * TT + t0 + tx] =
            __float2half_rn(t[tx][row]);
    }
}

__global__ __launch_bounds__(256) void prep_w(const float* __restrict__ w){
    __shared__ float t[32][33];
    const int k0 = blockIdx.x * 32, n0 = blockIdx.y * 32;
    const int tx = threadIdx.x & 31, ty = threadIdx.x >> 5;
    #pragma unroll
    for (int i = 0; i < 4; i++){
        const int row = ty + 8 * i;
        t[row][tx] = w[(size_t)(k0 + row) * CC + n0 + tx];
    }
    __syncthreads();
    #pragma unroll
    for (int i = 0; i < 4; i++){
        const int row = ty + 8 * i;   // n index within tile
        g_wTh[(size_t)(n0 + row) * NHC + k0 + tx] = __float2half_rn(t[tx][row]);
    }
}

// ---------------------------------------------------------------------------
extern "C" void kernel_launch(void* const* d_in, const int* in_sizes, int n_in,
                              void* d_out, int out_size) {
    const float* x = (const float*)d_in[0];
    const float* w = (const float*)d_in[1];
    float* out = (float*)d_out;

    const int SMEM_S = 3 * 16384;   // scores: A + 2 B buffers = 48 KB
    const int SMEM_G = 3 * 32768;   // pipelined GEMMs: 96 KB
    cudaFuncSetAttribute(scores_mma, cudaFuncAttributeMaxDynamicSharedMemorySize, SMEM_S);
    cudaFuncSetAttribute(pv_mma,     cudaFuncAttributeMaxDynamicSharedMemorySize, SMEM_G);
    cudaFuncSetAttribute(proj_mma,   cudaFuncAttributeMaxDynamicSharedMemorySize, SMEM_G);

    zero_sum<<<(BB*NH*TT)/256, 256>>>();
    prep_x<<<dim3(TT/32, CC/32, BB), 256>>>(x);
    prep_w<<<dim3(NHC/32, CC/32), 256>>>(w);
    scores_mma<<<dim3(TT/512, TT/128, BB*NH), 256, SMEM_S>>>();
    pv_mma<<<dim3(CC/128, TT/128, BB*NH), 256, SMEM_G>>>();
    proj_mma<<<dim3(CC/128, (BB*TT)/128), 256, SMEM_G>>>(out);
}